// round 1
// baseline (speedup 1.0000x reference)
#include <cuda_runtime.h>
#include <math.h>

#define N_MAX   65536
#define NF      64
#define LORD    5
#define RING    1024
#define BLOCK   128
#define ZCLAMP  801   // COEFF_VEC_SIZE(807) - (L_ORDER+1)

// ---------------- device scratch (no allocations allowed) ----------------
__device__ __align__(16) float4 g_vals4[N_MAX * 2];  // 8 floats per sample (6 used)
__device__ int   g_zc[N_MAX];
__device__ float g_x[N_MAX];
__device__ int   g_minz;
__device__ float g_spy[6][64];
__device__ float g_spb[6][63];
__device__ float g_spc[6][63];
__device__ float g_spd[6][63];

__device__ __forceinline__ float tin_f(int i) {
    // fp32 knot position, matching jnp.linspace(0,1,64)[i] to ~1 ulp
    return (float)((double)i / 63.0);
}

// ---------------- kernel 1: coeffs + spline solve (tiny) ----------------
__global__ void prep_kernel(const float* __restrict__ delay,
                            const float* __restrict__ raw) {
    __shared__ float yf[6][NF];
    __shared__ double w[62];
    int tid = threadIdx.x;
    if (tid == 0) g_minz = 0x7fffffff;   // reset per launch (graph replay safe)

    if (tid < NF) {
        float s[LORD]; float sum = 0.f;
        #pragma unroll
        for (int l = 0; l < LORD; l++) {
            s[l] = 1.0f / (1.0f + expf(-raw[tid * LORD + l]));
            sum += s[l];
        }
        #pragma unroll
        for (int l = 0; l < LORD; l++) yf[1 + l][tid] = s[l] / sum;
        yf[0][tid] = delay[tid];
    }
    __syncthreads();

    if (tid == 0) {
        // Thomas precompute for system M[i-1] + 4 M[i] + M[i+1] = r_i  (62 unknowns)
        w[0] = 0.25;
        for (int k = 1; k < 62; k++) w[k] = 1.0 / (4.0 - w[k - 1]);
    }
    __syncthreads();

    if (tid < 6) {
        const double h  = 1.0 / 63.0;
        const double rs = 6.0 / (h * h);
        double dp[62];
        double yim1 = (double)yf[tid][0];
        double yi   = (double)yf[tid][1];
        for (int k = 0; k < 62; k++) {
            double yip1 = (double)yf[tid][k + 2];
            double r = rs * (yip1 - 2.0 * yi + yim1);
            dp[k] = (k == 0) ? r * w[0] : (r - dp[k - 1]) * w[k];
            yim1 = yi; yi = yip1;
        }
        double M[64];
        M[0] = 0.0; M[63] = 0.0;
        M[62] = dp[61];
        for (int k = 60; k >= 0; k--) M[k + 1] = dp[k] - w[k] * M[k + 2];

        for (int i = 0; i < 63; i++) {
            double y0 = (double)yf[tid][i], y1 = (double)yf[tid][i + 1];
            double b = (y1 - y0) / h - h * (2.0 * M[i] + M[i + 1]) / 6.0;
            double c = M[i] * 0.5;
            double d = (M[i + 1] - M[i]) / (6.0 * h);
            g_spy[tid][i] = (float)y0;
            g_spb[tid][i] = (float)b;
            g_spc[tid][i] = (float)c;
            g_spd[tid][i] = (float)d;
        }
        g_spy[tid][63] = yf[tid][63];
    }
}

// ---------------- kernel 2: spline eval + filter taps ----------------
__global__ void interp_kernel(const float* __restrict__ exc, int burst, int n) {
    int j = blockIdx.x * blockDim.x + threadIdx.x;
    int stride = gridDim.x * blockDim.x;
    int localmin = 0x7fffffff;
    double inv_nm1 = 1.0 / (double)(n - 1);

    for (; j < n; j += stride) {
        double td = (double)j * inv_nm1;
        float tf = (float)td;
        int i0 = (int)(td * 63.0);
        if (i0 > 62) i0 = 62;
        if (i0 < 0)  i0 = 0;
        // replicate searchsorted(t_in, t_out, 'right')-1 in fp32 exactly
        while (i0 < 62 && tin_f(i0 + 1) <= tf) i0++;
        while (i0 > 0 && tin_f(i0) > tf) i0--;
        float dt = tf - tin_f(i0);

        float ch[6];
        #pragma unroll
        for (int c = 0; c < 6; c++) {
            float y0 = g_spy[c][i0];
            float b  = g_spb[c][i0];
            float cc = g_spc[c][i0];
            float dd = g_spd[c][i0];
            ch[c] = y0 + b * dt + cc * dt * dt + dd * dt * dt * dt;
        }

        float delay = ch[0];
        float zf = floorf(delay);
        int   z  = (int)zf;
        float alfa = delay - zf;
        float om = 1.0f - alfa;
        float b0 = ch[1], b1 = ch[2], b2 = ch[3], b3 = ch[4], b4 = ch[5];

        float4 vA = make_float4(-om * b0,
                                -(alfa * b0 + om * b1),
                                -(alfa * b1 + om * b2),
                                -(alfa * b2 + om * b3));
        float4 vB = make_float4(-(alfa * b3 + om * b4),
                                -alfa * b4, 0.f, 0.f);
        g_vals4[(size_t)j * 2]     = vA;
        g_vals4[(size_t)j * 2 + 1] = vB;

        int zc = z; if (zc < 0) zc = 0; if (zc > ZCLAMP) zc = ZCLAMP;
        g_zc[j] = zc;
        g_x[j]  = (j < burst) ? exc[j] : 0.0f;
        if (zc < localmin) localmin = zc;
    }
    atomicMin(&g_minz, localmin);
}

// ---------------- kernel 3: chunked sequential IIR ----------------
__global__ void __launch_bounds__(BLOCK, 1)
iir_kernel(float* __restrict__ out, int n) {
    __shared__ float ring[RING];
    int tid = threadIdx.x;
    for (int i = tid; i < RING; i += BLOCK) ring[i] = 0.0f;

    int W = g_minz + 1;            // safe parallel window (nearest feedback tap)
    if (W > BLOCK) W = BLOCK;
    if (W < 1)     W = 1;
    __syncthreads();

    // prefetch chunk 0 tap data into registers
    float4 vA = make_float4(0, 0, 0, 0), vB = vA;
    int zz = 0; float xx = 0.f;
    if (tid < W && tid < n) {
        vA = g_vals4[(size_t)tid * 2];
        vB = g_vals4[(size_t)tid * 2 + 1];
        zz = g_zc[tid];
        xx = g_x[tid];
    }

    for (int c = 0; c < n; c += W) {
        int t = c + tid;
        // prefetch next chunk (independent LDGs — hidden behind LDS/FFMA/bar)
        int tn = t + W;
        float4 nA = make_float4(0, 0, 0, 0), nB = nA;
        int nz = 0; float nx = 0.f;
        if (tid < W && tn < n) {
            nA = g_vals4[(size_t)tn * 2];
            nB = g_vals4[(size_t)tn * 2 + 1];
            nz = g_zc[tn];
            nx = g_x[tn];
        }

        if (tid < W && t < n) {
            int base = t - 1 - zz;   // may be negative early: maps to still-zero slots
            float acc = xx;
            acc -= vA.x * ring[(base    ) & (RING - 1)];
            acc -= vA.y * ring[(base - 1) & (RING - 1)];
            acc -= vA.z * ring[(base - 2) & (RING - 1)];
            acc -= vA.w * ring[(base - 3) & (RING - 1)];
            acc -= vB.x * ring[(base - 4) & (RING - 1)];
            acc -= vB.y * ring[(base - 5) & (RING - 1)];
            // safe to write without an extra barrier: write slots alias only
            // samples <= c-896, reads touch only [c-807, c) + untouched zeros
            ring[t & (RING - 1)] = acc;
            out[t] = acc;
        }
        __syncthreads();   // one barrier per chunk: order writes before next reads
        vA = nA; vB = nB; zz = nz; xx = nx;
    }
}

// ---------------- launch ----------------
extern "C" void kernel_launch(void* const* d_in, const int* in_sizes, int n_in,
                              void* d_out, int out_size) {
    const float* delay = (const float*)d_in[0];
    const float* raw   = (const float*)d_in[1];
    const float* exc   = (const float*)d_in[2];
    int burst = in_sizes[2];
    int n = out_size;
    if (n > N_MAX) n = N_MAX;

    prep_kernel<<<1, 128>>>(delay, raw);
    interp_kernel<<<64, 256>>>(exc, burst, n);
    iir_kernel<<<1, BLOCK>>>((float*)d_out, n);
}

// round 3
// speedup vs baseline: 1.9939x; 1.9939x over previous
#include <cuda_runtime.h>
#include <math.h>

#define N_MAX   65536
#define NF      64
#define LORD    5
#define RING    2048
#define BLOCK   512
#define M32N    (N_MAX / 32)
#define ZCLAMP  801   // COEFF_VEC_SIZE(807) - (L_ORDER+1)

// ---------------- device scratch (no allocations allowed) ----------------
__device__ __align__(16) float4 g_vals4[N_MAX * 2];  // per sample: v0..v5, x, z_bits
__device__ int   g_m32[M32N];                        // min clamped z per 32-sample block
__device__ float g_spy[6][64];
__device__ float g_spb[6][63];
__device__ float g_spc[6][63];
__device__ float g_spd[6][63];

__device__ __forceinline__ float tin_f(int i) {
    // fp32 knot position, matching jnp.linspace(0,1,64)[i] to ~1 ulp
    return (float)((double)i / 63.0);
}

// ---------------- kernel 1: coeffs + spline solve (fp32 Thomas) ----------------
__global__ void prep_kernel(const float* __restrict__ delay,
                            const float* __restrict__ raw) {
    __shared__ float yf[6][NF];
    __shared__ float w[62];
    int tid = threadIdx.x;

    // reset m32 table (graph-replay safe)
    for (int i = tid; i < M32N; i += 128) g_m32[i] = 0x7fffffff;

    if (tid < NF) {
        float s[LORD]; float sum = 0.f;
        #pragma unroll
        for (int l = 0; l < LORD; l++) {
            s[l] = 1.0f / (1.0f + expf(-raw[tid * LORD + l]));
            sum += s[l];
        }
        #pragma unroll
        for (int l = 0; l < LORD; l++) yf[1 + l][tid] = s[l] / sum;
        yf[0][tid] = delay[tid];
    }
    __syncthreads();

    if (tid == 0) {
        float wv = 0.25f; w[0] = wv;
        for (int k = 1; k < 62; k++) { wv = 1.0f / (4.0f - wv); w[k] = wv; }
    }
    __syncthreads();

    if (tid < 6) {
        const float h  = 1.0f / 63.0f;
        const float rs = 6.0f * 63.0f * 63.0f;   // 6/h^2
        float dp[62];
        float yim1 = yf[tid][0];
        float yi   = yf[tid][1];
        #pragma unroll
        for (int k = 0; k < 62; k++) {
            float yip1 = yf[tid][k + 2];
            float r = rs * (yip1 - 2.0f * yi + yim1);
            dp[k] = (k == 0) ? r * w[0] : (r - dp[k - 1]) * w[k];
            yim1 = yi; yi = yip1;
        }
        // backward sweep: M[63]=0, M[62]=dp[61], M[k+1]=dp[k]-w[k]*M[k+2]
        float M[64];
        M[63] = 0.0f;
        M[62] = dp[61];
        #pragma unroll
        for (int k = 60; k >= 0; k--) M[k + 1] = dp[k] - w[k] * M[k + 2];
        M[0] = 0.0f;

        #pragma unroll
        for (int i = 0; i < 63; i++) {
            float y0 = yf[tid][i], y1 = yf[tid][i + 1];
            float b = (y1 - y0) * 63.0f - h * (2.0f * M[i] + M[i + 1]) * (1.0f / 6.0f);
            float c = M[i] * 0.5f;
            float d = (M[i + 1] - M[i]) * (63.0f / 6.0f);
            g_spy[tid][i] = y0;
            g_spb[tid][i] = b;
            g_spc[tid][i] = c;
            g_spd[tid][i] = d;
        }
        g_spy[tid][63] = yf[tid][63];
    }
}

// ---------------- kernel 2: spline eval + filter taps + m32 ----------------
__global__ void interp_kernel(const float* __restrict__ exc, int burst, int n) {
    int j = blockIdx.x * blockDim.x + threadIdx.x;
    int stride = gridDim.x * blockDim.x;
    double inv_nm1 = 1.0 / (double)(n - 1);
    if (burst > n) burst = n;

    for (; j < n; j += stride) {
        double td = (double)j * inv_nm1;
        float tf = (float)td;
        int i0 = (int)(td * 63.0);
        if (i0 > 62) i0 = 62;
        if (i0 < 0)  i0 = 0;
        // replicate searchsorted(t_in, t_out, 'right')-1 in fp32 exactly
        while (i0 < 62 && tin_f(i0 + 1) <= tf) i0++;
        while (i0 > 0 && tin_f(i0) > tf) i0--;
        float dt = tf - tin_f(i0);

        float ch[6];
        #pragma unroll
        for (int c = 0; c < 6; c++) {
            float y0 = g_spy[c][i0];
            float b  = g_spb[c][i0];
            float cc = g_spc[c][i0];
            float dd = g_spd[c][i0];
            ch[c] = y0 + b * dt + cc * dt * dt + dd * dt * dt * dt;
        }

        float delay = ch[0];
        float zf = floorf(delay);
        int   z  = (int)zf;
        float alfa = delay - zf;
        float om = 1.0f - alfa;
        float b0 = ch[1], b1 = ch[2], b2 = ch[3], b3 = ch[4], b4 = ch[5];

        int zc = z; if (zc < 0) zc = 0; if (zc > ZCLAMP) zc = ZCLAMP;
        float x = (j < burst) ? exc[j] : 0.0f;

        float4 vA = make_float4(-om * b0,
                                -(alfa * b0 + om * b1),
                                -(alfa * b1 + om * b2),
                                -(alfa * b2 + om * b3));
        float4 vB = make_float4(-(alfa * b3 + om * b4),
                                -alfa * b4,
                                x,
                                __int_as_float(zc));
        g_vals4[(size_t)j * 2]     = vA;
        g_vals4[(size_t)j * 2 + 1] = vB;

        atomicMin(&g_m32[j >> 5], zc);
    }
}

// ---------------- kernel 3: variable-width chunked IIR ----------------
__global__ void __launch_bounds__(BLOCK, 1)
iir_kernel(float* __restrict__ out, int n) {
    __shared__ float ring[RING];
    __shared__ int   sm32[M32N];
    __shared__ int   sW[2];
    int tid = threadIdx.x;
    const float4* __restrict__ vals = g_vals4;

    for (int i = tid; i < RING; i += BLOCK) ring[i] = 0.0f;
    for (int i = tid; i < M32N; i += BLOCK) sm32[i] = g_m32[i];
    __syncthreads();

    // W for chunk 0: min of m32 over [0, 544) -> 17 blocks of 32
    if (tid < 32) {
        int v = (tid < 17 && tid < M32N) ? sm32[tid] : 0x7fffffff;
        v = __reduce_min_sync(0xffffffffu, v);
        if (tid == 0) {
            int W0 = v + 1;
            if (W0 > BLOCK) W0 = BLOCK;
            if (W0 < 1)     W0 = 1;
            sW[0] = W0;
        }
    }
    // prefetch chunk 0 sample data
    float4 cA = make_float4(0, 0, 0, 0), cB = make_float4(0, 0, 0, 0);
    if (tid < n) {
        cA = vals[(size_t)tid * 2];
        cB = vals[(size_t)tid * 2 + 1];
    }
    __syncthreads();

    int c = 0;
    int parity = 0;
    int W = sW[0];

    while (c < n) {
        int cn = c + W;

        // warp 0: compute W(cn) for next chunk (17 LDS + redux, off the main path)
        if (tid < 32) {
            int idx = (cn >> 5) + tid;
            int v = (tid < 17 && idx < M32N) ? sm32[idx] : 0x7fffffff;
            v = __reduce_min_sync(0xffffffffu, v);
            if (tid == 0) {
                int Wn = v + 1;
                if (Wn > BLOCK) Wn = BLOCK;
                if (Wn < 1)     Wn = 1;
                sW[parity ^ 1] = Wn;
            }
        }

        // prefetch next chunk sample data (L2 latency hidden under this chunk)
        int tn = cn + tid;
        float4 pA = make_float4(0, 0, 0, 0), pB = make_float4(0, 0, 0, 0);
        if (tn < n) {
            pA = vals[(size_t)tn * 2];
            pB = vals[(size_t)tn * 2 + 1];
        }

        // body: one sample per thread; ring reads are unconditional (masked
        // addresses always in range; values from lanes >= W are discarded)
        int t = c + tid;
        int zz = __float_as_int(cB.w);
        int base = t - 1 - zz;
        float r0 = ring[(base    ) & (RING - 1)];
        float r1 = ring[(base - 1) & (RING - 1)];
        float r2 = ring[(base - 2) & (RING - 1)];
        float r3 = ring[(base - 3) & (RING - 1)];
        float r4 = ring[(base - 4) & (RING - 1)];
        float r5 = ring[(base - 5) & (RING - 1)];
        float acc = cB.z;
        acc -= cA.x * r0;
        acc -= cA.y * r1;
        acc -= cA.z * r2;
        acc -= cA.w * r3;
        acc -= cB.x * r4;
        acc -= cB.y * r5;
        if (tid < W && t < n) {
            // write slots alias only samples <= c-1536; reads reach >= c-807
            ring[t & (RING - 1)] = acc;
            out[t] = acc;
        }
        __syncthreads();   // single barrier per chunk: publishes ring + sW

        c = cn;
        W = sW[parity ^ 1];
        parity ^= 1;
        cA = pA; cB = pB;
    }
}

// ---------------- launch ----------------
extern "C" void kernel_launch(void* const* d_in, const int* in_sizes, int n_in,
                              void* d_out, int out_size) {
    const float* delay = (const float*)d_in[0];
    const float* raw   = (const float*)d_in[1];
    const float* exc   = (const float*)d_in[2];
    int burst = in_sizes[2];
    int n = out_size;
    if (n > N_MAX) n = N_MAX;

    prep_kernel<<<1, 128>>>(delay, raw);
    interp_kernel<<<64, 256>>>(exc, burst, n);
    iir_kernel<<<1, BLOCK>>>((float*)d_out, n);
}

// round 4
// speedup vs baseline: 2.2467x; 1.1268x over previous
#include <cuda_runtime.h>
#include <math.h>

#define N_MAX   65536
#define NF      64
#define LORD    5
#define RING    2048
#define BLOCK   512
#define M32N    (N_MAX / 32)
#define ZCLAMP  801          // COEFF_VEC_SIZE(807) - (L_ORDER+1)
#define IB_SAMP 1024         // samples per interp block
#define IB_THR  256

// ---------------- device scratch (no allocations allowed) ----------------
__device__ __align__(16) float4 g_vals4[N_MAX * 2];  // per sample: v0..v5, x, z_bits
__device__ int g_m32[M32N];                          // min clamped z per 32-sample block

__device__ __forceinline__ float tin_f(int i) {
    // fp32 knot position, matching jnp.linspace(0,1,64)[i] to ~1 ulp
    return (float)((double)i / 63.0);
}

// ---------------- kernel 1: fused prep (per-block) + spline eval + taps ----------------
__global__ void __launch_bounds__(IB_THR)
interp_kernel(const float* __restrict__ delay, const float* __restrict__ raw,
              const float* __restrict__ exc, int burst, int n) {
    __shared__ float yf[6][NF];
    __shared__ float w[62];
    __shared__ float dpS[6][62];
    __shared__ float Ms[6][64];
    __shared__ float spy[6][64];
    __shared__ float spb[6][63];
    __shared__ float spc[6][63];
    __shared__ float spd[6][63];
    int tid = threadIdx.x;
    if (burst > n) burst = n;

    // --- phase 1: sigmoid coeffs (threads 0..63) + Thomas w table (one spare thread)
    if (tid < NF) {
        float s[LORD]; float sum = 0.f;
        #pragma unroll
        for (int l = 0; l < LORD; l++) {
            s[l] = 1.0f / (1.0f + expf(-raw[tid * LORD + l]));
            sum += s[l];
        }
        #pragma unroll
        for (int l = 0; l < LORD; l++) yf[1 + l][tid] = s[l] / sum;
        yf[0][tid] = delay[tid];
    }
    if (tid == IB_THR - 1) {
        float wv = 0.25f; w[0] = wv;
        #pragma unroll
        for (int k = 1; k < 62; k++) { wv = 1.0f / (4.0f - wv); w[k] = wv; }
    }
    __syncthreads();

    // --- phase 2: Thomas forward/backward (6 threads, scratch in shared)
    if (tid < 6) {
        const float rs = 6.0f * 63.0f * 63.0f;   // 6/h^2
        float yim1 = yf[tid][0];
        float yi   = yf[tid][1];
        float prev = 0.f;
        #pragma unroll
        for (int k = 0; k < 62; k++) {
            float yip1 = yf[tid][k + 2];
            float r = rs * (yip1 - 2.0f * yi + yim1);
            prev = (k == 0) ? r * w[0] : (r - prev) * w[k];
            dpS[tid][k] = prev;
            yim1 = yi; yi = yip1;
        }
        Ms[tid][63] = 0.0f;
        Ms[tid][0]  = 0.0f;
        float mnext = dpS[tid][61];
        Ms[tid][62] = mnext;
        #pragma unroll
        for (int k = 60; k >= 0; k--) {
            mnext = dpS[tid][k] - w[k] * Ms[tid][k + 2];
            Ms[tid][k + 1] = mnext;
        }
        spy[tid][63] = yf[tid][63];
    }
    __syncthreads();

    // --- phase 3: emit interval coefficients (parallel over 6*63)
    for (int e = tid; e < 6 * 63; e += IB_THR) {
        int ch = e / 63, i = e - ch * 63;
        float y0 = yf[ch][i], y1 = yf[ch][i + 1];
        float M0 = Ms[ch][i], M1 = Ms[ch][i + 1];
        float b = (y1 - y0) * 63.0f - (1.0f / 63.0f) * (2.0f * M0 + M1) * (1.0f / 6.0f);
        spy[ch][i] = y0;
        spb[ch][i] = b;
        spc[ch][i] = M0 * 0.5f;
        spd[ch][i] = (M1 - M0) * (63.0f / 6.0f);
    }
    __syncthreads();

    // --- phase 4: evaluate 4 consecutive samples per thread
    const double inv_nm1 = 1.0 / (double)(n - 1);
    int j0 = blockIdx.x * IB_SAMP + tid * 4;
    int zmin = 0x7fffffff;

    #pragma unroll
    for (int q = 0; q < 4; q++) {
        int j = j0 + q;
        if (j >= n) break;
        double td = (double)j * inv_nm1;
        float tf = (float)td;
        int i0 = (int)(td * 63.0);
        if (i0 > 62) i0 = 62;
        if (i0 < 0)  i0 = 0;
        // replicate searchsorted(t_in, t_out, 'right')-1 in fp32 exactly
        while (i0 < 62 && tin_f(i0 + 1) <= tf) i0++;
        while (i0 > 0 && tin_f(i0) > tf) i0--;
        float dt = tf - tin_f(i0);

        float ch[6];
        #pragma unroll
        for (int cc = 0; cc < 6; cc++) {
            ch[cc] = spy[cc][i0] + spb[cc][i0] * dt
                   + spc[cc][i0] * dt * dt + spd[cc][i0] * dt * dt * dt;
        }

        float dl = ch[0];
        float zf = floorf(dl);
        int   z  = (int)zf;
        float alfa = dl - zf;
        float om = 1.0f - alfa;
        float b0 = ch[1], b1 = ch[2], b2 = ch[3], b3 = ch[4], b4 = ch[5];

        int zc = z; if (zc < 0) zc = 0; if (zc > ZCLAMP) zc = ZCLAMP;
        float x = (j < burst) ? exc[j] : 0.0f;

        float4 vA = make_float4(-om * b0,
                                -(alfa * b0 + om * b1),
                                -(alfa * b1 + om * b2),
                                -(alfa * b2 + om * b3));
        float4 vB = make_float4(-(alfa * b3 + om * b4),
                                -alfa * b4,
                                x,
                                __int_as_float(zc));
        g_vals4[(size_t)j * 2]     = vA;
        g_vals4[(size_t)j * 2 + 1] = vB;
        if (zc < zmin) zmin = zc;
    }

    // min over 8 consecutive lanes = one 32-sample block; no atomics needed
    #pragma unroll
    for (int off = 4; off; off >>= 1) {
        int o = __shfl_xor_sync(0xffffffffu, zmin, off);
        if (o < zmin) zmin = o;
    }
    if ((tid & 7) == 0) {
        int mi = j0 >> 5;
        if (mi < M32N) g_m32[mi] = zmin;
    }
}

// ---------------- kernel 2: variable-width chunked IIR, two-ahead schedule ----------------
__global__ void __launch_bounds__(BLOCK, 1)
iir_kernel(float* __restrict__ out, int n) {
    __shared__ float ring[RING];
    __shared__ int   sm32[M32N];
    __shared__ int   swb[M32N];   // chunk width if a chunk starts in this 32-block
    int tid = threadIdx.x;
    const float4* __restrict__ vals = g_vals4;

    for (int i = tid; i < RING; i += BLOCK) ring[i] = 0.0f;
    for (int i = tid; i < M32N; i += BLOCK) sm32[i] = g_m32[i];
    __syncthreads();

    // Wb[i] = min(m32[i .. i+17]) + 1  (covers any start within block i + 544 span)
    for (int i = tid; i < M32N; i += BLOCK) {
        int v = 0x7fffffff;
        #pragma unroll
        for (int k = 0; k < 18; k++) {
            int idx = i + k;
            if (idx < M32N) { int m = sm32[idx]; if (m < v) v = m; }
        }
        int Wv = v + 1;
        if (Wv > BLOCK) Wv = BLOCK;
        if (Wv < 1)     Wv = 1;
        swb[i] = Wv;
    }
    __syncthreads();

    // schedule prologue: widths of chunk 0 and 1, prefetch chunk 0
    int Wc = swb[0];
    int Wn = swb[Wc >> 5];
    float4 cA = make_float4(0, 0, 0, 0), cB = make_float4(0, 0, 0, 0);
    if (tid < Wc && tid < n) {
        cA = vals[(size_t)tid * 2];
        cB = vals[(size_t)tid * 2 + 1];
    }

    int c = 0;
    while (c < n) {
        int cn  = c + Wc;
        int cn2 = cn + Wn;
        int i2 = cn2 >> 5; if (i2 > M32N - 1) i2 = M32N - 1;
        int W2 = swb[i2];                    // broadcast LDS, off the critical path

        // prefetch chunk k+1: gate and base both known now (two-ahead widths)
        float4 pA = make_float4(0, 0, 0, 0), pB = make_float4(0, 0, 0, 0);
        int tn = cn + tid;
        if (tid < Wn && tn < n) {
            pA = vals[(size_t)tn * 2];
            pB = vals[(size_t)tn * 2 + 1];
        }

        // body: fully gated — inactive warps go straight to the barrier
        int t = c + tid;
        if (tid < Wc && t < n) {
            int zz = __float_as_int(cB.w);
            int base = t - 1 - zz;
            float r0 = ring[(base    ) & (RING - 1)];
            float r1 = ring[(base - 1) & (RING - 1)];
            float r2 = ring[(base - 2) & (RING - 1)];
            float r3 = ring[(base - 3) & (RING - 1)];
            float r4 = ring[(base - 4) & (RING - 1)];
            float r5 = ring[(base - 5) & (RING - 1)];
            float acc = cB.z;
            acc -= cA.x * r0;
            acc -= cA.y * r1;
            acc -= cA.z * r2;
            acc -= cA.w * r3;
            acc -= cB.x * r4;
            acc -= cB.y * r5;
            // write slots alias only samples <= c-1536; reads reach >= c-807
            ring[t & (RING - 1)] = acc;
            out[t] = acc;
        }
        __syncthreads();   // single barrier per chunk

        c = cn; Wc = Wn; Wn = W2;
        cA = pA; cB = pB;
    }
}

// ---------------- launch ----------------
extern "C" void kernel_launch(void* const* d_in, const int* in_sizes, int n_in,
                              void* d_out, int out_size) {
    const float* delay = (const float*)d_in[0];
    const float* raw   = (const float*)d_in[1];
    const float* exc   = (const float*)d_in[2];
    int burst = in_sizes[2];
    int n = out_size;
    if (n > N_MAX) n = N_MAX;

    int iblocks = (n + IB_SAMP - 1) / IB_SAMP;
    interp_kernel<<<iblocks, IB_THR>>>(delay, raw, exc, burst, n);
    iir_kernel<<<1, BLOCK>>>((float*)d_out, n);
}

// round 5
// speedup vs baseline: 2.2756x; 1.0128x over previous
#include <cuda_runtime.h>
#include <math.h>

#define N_MAX   65536
#define NF      64
#define LORD    5
#define RING    2048
#define BLOCK   512
#define M32N    (N_MAX / 32)
#define ZCLAMP  801          // COEFF_VEC_SIZE(807) - (L_ORDER+1)
#define IB_SAMP 1024         // samples per interp block
#define IB_THR  256

// ---------------- device scratch (no allocations allowed) ----------------
__device__ __align__(16) float4 g_vals4[N_MAX * 2];  // per sample: v0..v5, x, z_bits
__device__ int g_m32[M32N];                          // min clamped z per 32-sample block

__device__ __forceinline__ float tin_f(int i) {
    // fp32 knot position, matching jnp.linspace(0,1,64)[i] to ~1 ulp
    return (float)((double)i / 63.0);
}

// ---------------- kernel 1: fused prep (per-block) + spline eval + taps ----------------
__global__ void __launch_bounds__(IB_THR)
interp_kernel(const float* __restrict__ delay, const float* __restrict__ raw,
              const float* __restrict__ exc, int burst, int n) {
    __shared__ float yf[6][NF];
    __shared__ float w[62];
    __shared__ float dpS[6][62];
    __shared__ float Ms[6][64];
    __shared__ float spy[6][64];
    __shared__ float spb[6][63];
    __shared__ float spc[6][63];
    __shared__ float spd[6][63];
    int tid = threadIdx.x;
    if (burst > n) burst = n;

    // --- phase 1: sigmoid coeffs (threads 0..63) + Thomas w table (one spare thread)
    if (tid < NF) {
        float s[LORD]; float sum = 0.f;
        #pragma unroll
        for (int l = 0; l < LORD; l++) {
            s[l] = 1.0f / (1.0f + expf(-raw[tid * LORD + l]));
            sum += s[l];
        }
        #pragma unroll
        for (int l = 0; l < LORD; l++) yf[1 + l][tid] = s[l] / sum;
        yf[0][tid] = delay[tid];
    }
    if (tid == IB_THR - 1) {
        float wv = 0.25f; w[0] = wv;
        #pragma unroll
        for (int k = 1; k < 62; k++) { wv = 1.0f / (4.0f - wv); w[k] = wv; }
    }
    __syncthreads();

    // --- phase 2: Thomas forward/backward (6 threads, scratch in shared)
    if (tid < 6) {
        const float rs = 6.0f * 63.0f * 63.0f;   // 6/h^2
        float yim1 = yf[tid][0];
        float yi   = yf[tid][1];
        float prev = 0.f;
        #pragma unroll
        for (int k = 0; k < 62; k++) {
            float yip1 = yf[tid][k + 2];
            float r = rs * (yip1 - 2.0f * yi + yim1);
            prev = (k == 0) ? r * w[0] : (r - prev) * w[k];
            dpS[tid][k] = prev;
            yim1 = yi; yi = yip1;
        }
        Ms[tid][63] = 0.0f;
        Ms[tid][0]  = 0.0f;
        float mnext = dpS[tid][61];
        Ms[tid][62] = mnext;
        #pragma unroll
        for (int k = 60; k >= 0; k--) {
            mnext = dpS[tid][k] - w[k] * Ms[tid][k + 2];
            Ms[tid][k + 1] = mnext;
        }
        spy[tid][63] = yf[tid][63];
    }
    __syncthreads();

    // --- phase 3: emit interval coefficients (parallel over 6*63)
    for (int e = tid; e < 6 * 63; e += IB_THR) {
        int ch = e / 63, i = e - ch * 63;
        float y0 = yf[ch][i], y1 = yf[ch][i + 1];
        float M0 = Ms[ch][i], M1 = Ms[ch][i + 1];
        float b = (y1 - y0) * 63.0f - (1.0f / 63.0f) * (2.0f * M0 + M1) * (1.0f / 6.0f);
        spy[ch][i] = y0;
        spb[ch][i] = b;
        spc[ch][i] = M0 * 0.5f;
        spd[ch][i] = (M1 - M0) * (63.0f / 6.0f);
    }
    __syncthreads();

    // --- phase 4: evaluate 4 consecutive samples per thread
    const double inv_nm1 = 1.0 / (double)(n - 1);
    int j0 = blockIdx.x * IB_SAMP + tid * 4;
    int zmin = 0x7fffffff;

    #pragma unroll
    for (int q = 0; q < 4; q++) {
        int j = j0 + q;
        if (j >= n) break;
        double td = (double)j * inv_nm1;
        float tf = (float)td;
        int i0 = (int)(td * 63.0);
        if (i0 > 62) i0 = 62;
        if (i0 < 0)  i0 = 0;
        // replicate searchsorted(t_in, t_out, 'right')-1 in fp32 exactly
        while (i0 < 62 && tin_f(i0 + 1) <= tf) i0++;
        while (i0 > 0 && tin_f(i0) > tf) i0--;
        float dt = tf - tin_f(i0);

        float ch[6];
        #pragma unroll
        for (int cc = 0; cc < 6; cc++) {
            ch[cc] = spy[cc][i0] + spb[cc][i0] * dt
                   + spc[cc][i0] * dt * dt + spd[cc][i0] * dt * dt * dt;
        }

        float dl = ch[0];
        float zf = floorf(dl);
        int   z  = (int)zf;
        float alfa = dl - zf;
        float om = 1.0f - alfa;
        float b0 = ch[1], b1 = ch[2], b2 = ch[3], b3 = ch[4], b4 = ch[5];

        int zc = z; if (zc < 0) zc = 0; if (zc > ZCLAMP) zc = ZCLAMP;
        float x = (j < burst) ? exc[j] : 0.0f;

        float4 vA = make_float4(-om * b0,
                                -(alfa * b0 + om * b1),
                                -(alfa * b1 + om * b2),
                                -(alfa * b2 + om * b3));
        float4 vB = make_float4(-(alfa * b3 + om * b4),
                                -alfa * b4,
                                x,
                                __int_as_float(zc));
        g_vals4[(size_t)j * 2]     = vA;
        g_vals4[(size_t)j * 2 + 1] = vB;
        if (zc < zmin) zmin = zc;
    }

    // min over 8 consecutive lanes = one 32-sample block; no atomics needed
    #pragma unroll
    for (int off = 4; off; off >>= 1) {
        int o = __shfl_xor_sync(0xffffffffu, zmin, off);
        if (o < zmin) zmin = o;
    }
    if ((tid & 7) == 0) {
        int mi = j0 >> 5;
        if (mi < M32N) g_m32[mi] = zmin;
    }
}

// ---------------- kernel 2: variable-width chunked IIR, depth-3 prefetch ----------------
__global__ void __launch_bounds__(BLOCK, 1)
iir_kernel(float* __restrict__ out, int n) {
    __shared__ float ring[RING];
    __shared__ int   sm32[M32N];
    __shared__ int   swb[M32N];   // chunk width if a chunk starts in this 32-block
    int tid = threadIdx.x;
    const float4* __restrict__ vals = g_vals4;

    for (int i = tid; i < RING; i += BLOCK) ring[i] = 0.0f;
    for (int i = tid; i < M32N; i += BLOCK) sm32[i] = g_m32[i];
    __syncthreads();

    // Wb[i] = min(m32[i .. i+17]) + 1  (covers any start within block i + 544 span)
    for (int i = tid; i < M32N; i += BLOCK) {
        int v = 0x7fffffff;
        #pragma unroll
        for (int k = 0; k < 18; k++) {
            int idx = i + k;
            if (idx < M32N) { int m = sm32[idx]; if (m < v) v = m; }
        }
        int Wv = v + 1;
        if (Wv > BLOCK) Wv = BLOCK;
        if (Wv < 1)     Wv = 1;
        swb[i] = Wv;
    }
    __syncthreads();

    // ---- static schedule prologue: chunks 0..3 and three in-flight buffers ----
    #define WB_AT(pos) swb[((pos) >> 5) < (M32N - 1) ? ((pos) >> 5) : (M32N - 1)]
    int c   = 0;        int Wc = WB_AT(0);
    int cn  = c  + Wc;  int Wn = WB_AT(cn);
    int cn2 = cn + Wn;  int W2 = WB_AT(cn2);
    int cn3 = cn2 + W2; int W3 = WB_AT(cn3);

    float4 cA = make_float4(0,0,0,0), cB = cA;   // chunk k
    float4 aA = make_float4(0,0,0,0), aB = aA;   // chunk k+1
    float4 bA = make_float4(0,0,0,0), bB = bA;   // chunk k+2
    if (tid < Wc && tid < n) {
        cA = vals[(size_t)tid * 2];
        cB = vals[(size_t)tid * 2 + 1];
    }
    {
        int t1 = cn + tid;
        if (tid < Wn && t1 < n) {
            aA = vals[(size_t)t1 * 2];
            aB = vals[(size_t)t1 * 2 + 1];
        }
        int t2 = cn2 + tid;
        if (tid < W2 && t2 < n) {
            bA = vals[(size_t)t2 * 2];
            bB = vals[(size_t)t2 * 2 + 1];
        }
    }

    while (c < n) {
        // schedule one more chunk ahead (broadcast LDS, one chunk of slack)
        int cn4 = cn3 + W3;
        int W4  = WB_AT(cn4);

        // prefetch chunk k+3 (issued 3 chunks before use -> LDG latency hidden)
        float4 qA = make_float4(0,0,0,0), qB = qA;
        int t3 = cn3 + tid;
        if (tid < W3 && t3 < n) {
            qA = vals[(size_t)t3 * 2];
            qB = vals[(size_t)t3 * 2 + 1];
        }

        // body: fully gated — inactive warps go straight to the barrier
        int t = c + tid;
        if (tid < Wc && t < n) {
            int zz = __float_as_int(cB.w);
            int base = t - 1 - zz;
            float r0 = ring[(base    ) & (RING - 1)];
            float r1 = ring[(base - 1) & (RING - 1)];
            float r2 = ring[(base - 2) & (RING - 1)];
            float r3 = ring[(base - 3) & (RING - 1)];
            float r4 = ring[(base - 4) & (RING - 1)];
            float r5 = ring[(base - 5) & (RING - 1)];
            // two parallel FFMA chains, join at the end
            float s0 = cA.x * r0 + cA.z * r2 + cB.x * r4;
            float s1 = cA.y * r1 + cA.w * r3 + cB.y * r5;
            float acc = cB.z - s0 - s1;
            // write slots alias only samples <= c-1536; reads reach >= c-807
            ring[t & (RING - 1)] = acc;
            out[t] = acc;
        }
        __syncthreads();   // single barrier per chunk

        // rotate schedule + buffers
        c = cn; cn = cn2; cn2 = cn3; cn3 = cn4;
        Wc = Wn; Wn = W2; W2 = W3; W3 = W4;
        cA = aA; cB = aB;
        aA = bA; aB = bB;
        bA = qA; bB = qB;
    }
    #undef WB_AT
}

// ---------------- launch ----------------
extern "C" void kernel_launch(void* const* d_in, const int* in_sizes, int n_in,
                              void* d_out, int out_size) {
    const float* delay = (const float*)d_in[0];
    const float* raw   = (const float*)d_in[1];
    const float* exc   = (const float*)d_in[2];
    int burst = in_sizes[2];
    int n = out_size;
    if (n > N_MAX) n = N_MAX;

    int iblocks = (n + IB_SAMP - 1) / IB_SAMP;
    interp_kernel<<<iblocks, IB_THR>>>(delay, raw, exc, burst, n);
    iir_kernel<<<1, BLOCK>>>((float*)d_out, n);
}